// round 13
// baseline (speedup 1.0000x reference)
#include <cuda_runtime.h>
#include <cstdint>

#define NH   16
#define SEQ  2048
#define DIM  64
#define MT   128
#define CHUNK 64
#define NCH  (SEQ / CHUNK)       // 32
#define NTHREADS 256
#define SLG2E 0.18033688011112042f   // 0.125 * log2(e)

// ---- smem layout in u32 words ----
#define WKH   0u        // K-hi bf16x2, 2 bufs x 2304 (64 keys x 36)
#define WKL   4608u     // K-lo bf16x2, 2 bufs x 2304
#define WVT   9216u     // V tf32 paired, 2 bufs x 4096 (8 blk x 512)
#define WKST  17408u    // K raw staging 4096
#define WVST  21504u    // V raw staging 4096
#define SMEM_BYTES (25600u * 4u)   // 102400

__device__ float    g_inv_s[2 * NH * SEQ];
__device__ uint32_t g_mbits[2][SEQ][64];      // mask bitmap, 2 MB

// ---------------- helpers ----------------
__device__ __forceinline__ uint32_t tf32r(float x) {
    uint32_t r; asm("cvt.rna.tf32.f32 %0, %1;" : "=r"(r) : "f"(x)); return r;
}
__device__ __forceinline__ float ex2(float x) {
    float r; asm("ex2.approx.f32 %0, %1;" : "=f"(r) : "f"(x)); return r;
}
__device__ __forceinline__ uint32_t packbf(float lo, float hi) {
    uint32_t r; asm("cvt.rn.bf16x2.f32 %0, %1, %2;" : "=r"(r) : "f"(hi), "f"(lo)); return r;
}
__device__ __forceinline__ float lo_f(uint32_t r) { return __uint_as_float(r << 16); }
__device__ __forceinline__ float hi_f(uint32_t r) { return __uint_as_float(r & 0xffff0000u); }

__device__ __forceinline__ void mma16(float* d, const uint32_t* a, uint2 b) {
    asm("mma.sync.aligned.m16n8k16.row.col.f32.bf16.bf16.f32 "
        "{%0,%1,%2,%3}, {%4,%5,%6,%7}, {%8,%9}, {%0,%1,%2,%3};"
        : "+f"(d[0]), "+f"(d[1]), "+f"(d[2]), "+f"(d[3])
        : "r"(a[0]), "r"(a[1]), "r"(a[2]), "r"(a[3]), "r"(b.x), "r"(b.y));
}
__device__ __forceinline__ void mma8(float* d, const uint32_t* a, uint2 b) {
    asm("mma.sync.aligned.m16n8k8.row.col.f32.tf32.tf32.f32 "
        "{%0,%1,%2,%3}, {%4,%5,%6,%7}, {%8,%9}, {%0,%1,%2,%3};"
        : "+f"(d[0]), "+f"(d[1]), "+f"(d[2]), "+f"(d[3])
        : "r"(a[0]), "r"(a[1]), "r"(a[2]), "r"(a[3]), "r"(b.x), "r"(b.y));
}
__device__ __forceinline__ uint32_t smem_u32(const void* p) {
    uint32_t a;
    asm("{ .reg .u64 t; cvta.to.shared.u64 t, %1; cvt.u32.u64 %0, t; }" : "=r"(a) : "l"(p));
    return a;
}
__device__ __forceinline__ void cpasync16(uint32_t saddr, const void* g) {
    asm volatile("cp.async.cg.shared.global [%0], [%1], 16;" :: "r"(saddr), "l"(g) : "memory");
}
#define CP_COMMIT() asm volatile("cp.async.commit_group;" ::: "memory")
#define CP_WAIT0()  asm volatile("cp.async.wait_group 0;" ::: "memory")

// paired K address: unit u (d-pair index 0..15) -> key*36 + 8*(u>>3) + 2*((u&7)&3) + ((u&7)>>2)
__device__ __forceinline__ int kaddr(int key, int u) {
    int j = u & 7;
    return key * 36 + 8 * (u >> 3) + 2 * (j & 3) + (j >> 2);
}

// ---------------- kernel 0: mask -> bitmap ----------------
__global__ __launch_bounds__(256)
void mask_bits(const int* __restrict__ mask)
{
    int gw = blockIdx.x * 8 + (threadIdx.x >> 5);   // 0..65535, 4 words each
    int lane = threadIdx.x & 31;
    int m0 = mask[(size_t)(gw * 4 + 0) * 32 + lane];
    int m1 = mask[(size_t)(gw * 4 + 1) * 32 + lane];
    int m2 = mask[(size_t)(gw * 4 + 2) * 32 + lane];
    int m3 = mask[(size_t)(gw * 4 + 3) * 32 + lane];
    uint32_t b0 = __ballot_sync(0xffffffffu, m0 != 0);
    uint32_t b1 = __ballot_sync(0xffffffffu, m1 != 0);
    uint32_t b2 = __ballot_sync(0xffffffffu, m2 != 0);
    uint32_t b3 = __ballot_sync(0xffffffffu, m3 != 0);
    if (lane == 0) {
        uint32_t* dst = &g_mbits[0][0][0];
        uint4 vv = make_uint4(b0, b1, b2, b3);
        *(uint4*)(dst + gw * 4) = vv;
    }
}

// ---------------- kernel 1: attention (single pass) ----------------
__global__ __launch_bounds__(NTHREADS, 2)
void attn_sp(const float* __restrict__ q,
             const float* __restrict__ k,
             const float* __restrict__ v,
             float* __restrict__ out,
             float* __restrict__ p_attn)
{
    extern __shared__ uint32_t smw[];
    const uint32_t sbase = smem_u32(smw);

    const int tid  = threadIdx.x;
    const int lane = tid & 31;
    const int wid  = tid >> 5;
    const int lq   = lane >> 2;
    const int cq   = lane & 3;

    const int qt = blockIdx.x;     // 0..15
    const int bh = blockIdx.y;     // 0..31
    const int b  = bh / NH;

    const size_t qoff = ((size_t)bh * SEQ + (size_t)qt * MT) * DIM;
    const float* qg = q + qoff;
    const float4* k4 = (const float4*)(k + (size_t)bh * SEQ * DIM);
    const float4* v4 = (const float4*)(v + (size_t)bh * SEQ * DIM);
    float* outg = out + qoff;
    float* pg   = p_attn + ((size_t)bh * SEQ + (size_t)qt * MT) * SEQ;

    const int qb  = wid * 16;
    const int r0l = qb + lq;
    const int r1l = r0l + 8;

    // ---- issue cp.async for chunk 0 ----
    #pragma unroll
    for (int i = 0; i < 4; ++i) {
        int idx = tid + i * NTHREADS;
        cpasync16(sbase + (WKST + 4u * idx) * 4u, k4 + idx);
        cpasync16(sbase + (WVST + 4u * idx) * 4u, v4 + idx);
    }
    CP_COMMIT();

    // ---- Q rows r0l/r1l: scale, split to bf16 hi/lo frags (regs) ----
    uint32_t Qh[4][4], Ql[4][4];
    #pragma unroll
    for (int s = 0; s < 4; ++s) {
        #pragma unroll
        for (int part = 0; part < 2; ++part) {
            int col = 16 * s + 2 * cq + 8 * part;
            float2 qa  = *(const float2*)(qg + r0l * DIM + col);
            float2 qb2 = *(const float2*)(qg + r1l * DIM + col);
            qa.x *= SLG2E; qa.y *= SLG2E; qb2.x *= SLG2E; qb2.y *= SLG2E;
            uint32_t ha = packbf(qa.x, qa.y);
            uint32_t hb = packbf(qb2.x, qb2.y);
            Qh[s][0 + part * 2] = ha;
            Qh[s][1 + part * 2] = hb;
            Ql[s][0 + part * 2] = packbf(qa.x - lo_f(ha), qa.y - hi_f(ha));
            Ql[s][1 + part * 2] = packbf(qb2.x - lo_f(hb), qb2.y - hi_f(hb));
        }
    }

    const uint32_t* mb0 = &g_mbits[b][qt * MT + r0l][0];
    const uint32_t* mb1 = &g_mbits[b][qt * MT + r1l][0];
    uint2 mc0 = *(const uint2*)(mb0);
    uint2 mc1 = *(const uint2*)(mb1);

    float s0 = 0.f, s1 = 0.f;
    float oa[8][4];
    #pragma unroll
    for (int n = 0; n < 8; ++n)
        oa[n][0] = oa[n][1] = oa[n][2] = oa[n][3] = 0.f;

    const int src0 = lq * 4 + (cq >> 1);   // shuffle source for k=cq
    const int src2 = src0 + 2;             // for k=cq+4

    for (int c = 0; c < NCH; ++c) {
        const int buf = c & 1;
        uint32_t* KH = smw + WKH + buf * 2304;
        uint32_t* KL = smw + WKL + buf * 2304;
        uint32_t* VT = smw + WVT + buf * 4096;

        CP_WAIT0();          // staging for chunk c ready

        // ---- fill split buffers (paired layouts) from staging ----
        #pragma unroll
        for (int i = 0; i < 4; ++i) {
            int idx = tid + i * NTHREADS;
            int key = idx >> 4, u16 = idx & 15;
            float4 kv = *(float4*)(smw + WKST + 4 * idx);
            uint32_t hA = packbf(kv.x, kv.y), hB = packbf(kv.z, kv.w);
            uint32_t lA = packbf(kv.x - lo_f(hA), kv.y - hi_f(hA));
            uint32_t lB = packbf(kv.z - lo_f(hB), kv.w - hi_f(hB));
            int aA = kaddr(key, 2 * u16), aB = kaddr(key, 2 * u16 + 1);
            KH[aA] = hA; KH[aB] = hB;
            KL[aA] = lA; KL[aB] = lB;
            // V paired: (key, d) -> blk(key>>3)*512 + d*8 + (key&3)*2 + ((key>>2)&1)
            float4 vv = *(float4*)(smw + WVST + 4 * idx);
            int d0 = 4 * u16;
            uint32_t* vb = VT + (key >> 3) * 512 + ((key & 7) & 3) * 2 + ((key & 7) >> 2);
            vb[(d0 + 0) * 8] = tf32r(vv.x);
            vb[(d0 + 1) * 8] = tf32r(vv.y);
            vb[(d0 + 2) * 8] = tf32r(vv.z);
            vb[(d0 + 3) * 8] = tf32r(vv.w);
        }

        // ---- refill staging for chunk c+1 (each thread rewrites its own region) ----
        uint2 mn0 = mc0, mn1 = mc1;
        if (c + 1 < NCH) {
            #pragma unroll
            for (int i = 0; i < 4; ++i) {
                int idx = tid + i * NTHREADS;
                cpasync16(sbase + (WKST + 4u * idx) * 4u, k4 + (c + 1) * 1024 + idx);
                cpasync16(sbase + (WVST + 4u * idx) * 4u, v4 + (c + 1) * 1024 + idx);
            }
            CP_COMMIT();
            mn0 = *(const uint2*)(mb0 + 2 * (c + 1));
            mn1 = *(const uint2*)(mb1 + 2 * (c + 1));
        }

        __syncthreads();     // split buffers for c visible to all warps

        // ---- QK: bf16 3-term split ----
        float acc2[2][4][4];
        #pragma unroll
        for (int h = 0; h < 2; ++h)
            #pragma unroll
            for (int n = 0; n < 4; ++n)
                acc2[h][n][0] = acc2[h][n][1] = acc2[h][n][2] = acc2[h][n][3] = 0.f;

        #pragma unroll
        for (int s = 0; s < 4; ++s) {
            #pragma unroll
            for (int h = 0; h < 2; ++h)
                #pragma unroll
                for (int n = 0; n < 4; ++n) {
                    int base = (h * 32 + n * 8 + lq) * 36 + 8 * s + 2 * cq;
                    uint2 bh2 = *(uint2*)(KH + base);
                    uint2 bl2 = *(uint2*)(KL + base);
                    mma16(acc2[h][n], Qh[s], bh2);
                    mma16(acc2[h][n], Qh[s], bl2);
                    mma16(acc2[h][n], Ql[s], bh2);
                }
        }

        // ---- exp, s, p~ store, shuffle-exchange, PV (no smem staging) ----
        #pragma unroll
        for (int h = 0; h < 2; ++h) {
            uint32_t w0 = (h == 0) ? mc0.x : mc0.y;
            uint32_t w1 = (h == 0) ? mc1.x : mc1.y;
            #pragma unroll
            for (int n = 0; n < 4; ++n) {
                int bp = n * 8 + 2 * cq;
                float p00 = ((w0 >> bp)     & 1u) ? ex2(acc2[h][n][0]) : 0.f;
                float p01 = ((w0 >> (bp+1)) & 1u) ? ex2(acc2[h][n][1]) : 0.f;
                float p10 = ((w1 >> bp)     & 1u) ? ex2(acc2[h][n][2]) : 0.f;
                float p11 = ((w1 >> (bp+1)) & 1u) ? ex2(acc2[h][n][3]) : 0.f;
                s0 += p00 + p01;
                s1 += p10 + p11;
                int colg = c * CHUNK + h * 32 + n * 8 + 2 * cq;
                *(float2*)(pg + (size_t)r0l * SEQ + colg) = make_float2(p00, p01);
                *(float2*)(pg + (size_t)r1l * SEQ + colg) = make_float2(p10, p11);

                uint32_t t00 = tf32r(p00), t01 = tf32r(p01);
                uint32_t t10 = tf32r(p10), t11 = tf32r(p11);
                // C-frag -> A-frag exchange: a0=(lq,k=cq) a1=(lq+8,cq) a2=(lq,cq+4) a3=(lq+8,cq+4)
                uint32_t x0a = __shfl_sync(0xffffffffu, t00, src0);
                uint32_t y0a = __shfl_sync(0xffffffffu, t01, src0);
                uint32_t x0b = __shfl_sync(0xffffffffu, t00, src2);
                uint32_t y0b = __shfl_sync(0xffffffffu, t01, src2);
                uint32_t x1a = __shfl_sync(0xffffffffu, t10, src0);
                uint32_t y1a = __shfl_sync(0xffffffffu, t11, src0);
                uint32_t x1b = __shfl_sync(0xffffffffu, t10, src2);
                uint32_t y1b = __shfl_sync(0xffffffffu, t11, src2);
                uint32_t a[4];
                a[0] = (cq & 1) ? y0a : x0a;
                a[1] = (cq & 1) ? y1a : x1a;
                a[2] = (cq & 1) ? y0b : x0b;
                a[3] = (cq & 1) ? y1b : x1b;

                // PV for this 8-key group: kb = h*4+n
                const uint32_t* vb = VT + (h * 4 + n) * 512 + lq * 8 + cq * 2;
                #pragma unroll
                for (int n2 = 0; n2 < 8; ++n2) {
                    uint2 bb = *(const uint2*)(vb + n2 * 64);
                    mma8(oa[n2], a, bb);
                }
            }
        }

        mc0 = mn0; mc1 = mn1;
    }

    // ---- reduce s across quad lanes ----
    #pragma unroll
    for (int off = 1; off < 4; off <<= 1) {
        s0 += __shfl_xor_sync(0xffffffffu, s0, off);
        s1 += __shfl_xor_sync(0xffffffffu, s1, off);
    }
    const float inv0 = 1.f / s0;
    const float inv1 = 1.f / s1;

    if (cq == 0) {
        g_inv_s[(size_t)bh * SEQ + qt * MT + r0l] = inv0;
        g_inv_s[(size_t)bh * SEQ + qt * MT + r1l] = inv1;
    }

    #pragma unroll
    for (int n = 0; n < 8; ++n) {
        *(float2*)(outg + (size_t)r0l * DIM + n * 8 + 2 * cq) =
            make_float2(oa[n][0] * inv0, oa[n][1] * inv0);
        *(float2*)(outg + (size_t)r1l * DIM + n * 8 + 2 * cq) =
            make_float2(oa[n][2] * inv1, oa[n][3] * inv1);
    }
}

// ---------------- kernel 2: stream-rescale p_attn ----------------
__global__ __launch_bounds__(256)
void rescale_p(float* __restrict__ p_attn)
{
    unsigned i = blockIdx.x * 256u + threadIdx.x;   // float4 index
    unsigned row = i >> 9;                           // 512 float4 per row
    float inv = g_inv_s[row];
    float4* p4 = (float4*)p_attn;
    float4 vv = p4[i];
    vv.x *= inv; vv.y *= inv; vv.z *= inv; vv.w *= inv;
    p4[i] = vv;
}

extern "C" void kernel_launch(void* const* d_in, const int* in_sizes, int n_in,
                              void* d_out, int out_size)
{
    const float* q    = (const float*)d_in[0];
    const float* k    = (const float*)d_in[1];
    const float* v    = (const float*)d_in[2];
    const int*   mask = (const int*)d_in[3];

    float* out    = (float*)d_out;                              // [B,H,S,D]
    float* p_attn = (float*)d_out + (size_t)2 * NH * SEQ * DIM; // [B,H,S,S]

    mask_bits<<<8192, 256>>>(mask);

    cudaFuncSetAttribute(attn_sp,
                         cudaFuncAttributeMaxDynamicSharedMemorySize, SMEM_BYTES);
    dim3 grid(SEQ / MT, 2 * NH);    // (16, 32)
    attn_sp<<<grid, NTHREADS, SMEM_BYTES>>>(q, k, v, out, p_attn);

    rescale_p<<<131072, 256>>>(p_attn);
}

// round 14
// speedup vs baseline: 1.2755x; 1.2755x over previous
#include <cuda_runtime.h>
#include <cstdint>

#define NH   16
#define SEQ  2048
#define DIM  64
#define MT   128
#define CHUNK 64
#define NCH  (SEQ / CHUNK)       // 32
#define NTHREADS 256
#define SLG2E 0.18033688011112042f   // 0.125 * log2(e)

// ---- smem byte offsets (R9 layout) ----
#define OKH   0u                     // K-hi bf16x2 [64][36] u32  (9216 B)
#define OKL   9216u                  // K-lo bf16x2 [64][36] u32  (9216 B)
#define OVT   18432u                 // V tf32 [64][72]           (18432 B)
#define OPS   36864u                 // P tf32 [128][36]          (18432 B)
#define OKST  55296u                 // K raw staging 16384 B
#define OVST  71680u                 // V raw staging 16384 B
#define SMEM_BYTES 88064u

__device__ float    g_inv_s[2 * NH * SEQ];
__device__ uint32_t g_mbits[2][SEQ][64];      // mask bitmap, 2 MB

// ---------------- helpers ----------------
__device__ __forceinline__ uint32_t tf32r(float x) {
    uint32_t r; asm("cvt.rna.tf32.f32 %0, %1;" : "=r"(r) : "f"(x)); return r;
}
__device__ __forceinline__ float ex2(float x) {
    float r; asm("ex2.approx.f32 %0, %1;" : "=f"(r) : "f"(x)); return r;
}
__device__ __forceinline__ uint32_t packbf(float lo, float hi) {
    uint32_t r; asm("cvt.rn.bf16x2.f32 %0, %1, %2;" : "=r"(r) : "f"(hi), "f"(lo)); return r;
}
__device__ __forceinline__ float lo_f(uint32_t r) { return __uint_as_float(r << 16); }
__device__ __forceinline__ float hi_f(uint32_t r) { return __uint_as_float(r & 0xffff0000u); }

__device__ __forceinline__ void mma16(float* d, const uint32_t* a, const uint32_t* b) {
    asm("mma.sync.aligned.m16n8k16.row.col.f32.bf16.bf16.f32 "
        "{%0,%1,%2,%3}, {%4,%5,%6,%7}, {%8,%9}, {%0,%1,%2,%3};"
        : "+f"(d[0]), "+f"(d[1]), "+f"(d[2]), "+f"(d[3])
        : "r"(a[0]), "r"(a[1]), "r"(a[2]), "r"(a[3]), "r"(b[0]), "r"(b[1]));
}
__device__ __forceinline__ void mma8(float* d, const uint32_t* a, const uint32_t* b) {
    asm("mma.sync.aligned.m16n8k8.row.col.f32.tf32.tf32.f32 "
        "{%0,%1,%2,%3}, {%4,%5,%6,%7}, {%8,%9}, {%0,%1,%2,%3};"
        : "+f"(d[0]), "+f"(d[1]), "+f"(d[2]), "+f"(d[3])
        : "r"(a[0]), "r"(a[1]), "r"(a[2]), "r"(a[3]), "r"(b[0]), "r"(b[1]));
}
__device__ __forceinline__ uint32_t smem_u32(const void* p) {
    uint32_t a;
    asm("{ .reg .u64 t; cvta.to.shared.u64 t, %1; cvt.u32.u64 %0, t; }" : "=r"(a) : "l"(p));
    return a;
}
__device__ __forceinline__ void cpasync16(uint32_t saddr, const void* g) {
    asm volatile("cp.async.cg.shared.global [%0], [%1], 16;" :: "r"(saddr), "l"(g) : "memory");
}
#define CP_COMMIT() asm volatile("cp.async.commit_group;" ::: "memory")
#define CP_WAIT0()  asm volatile("cp.async.wait_group 0;" ::: "memory")

__device__ __forceinline__ void stg_cs2(float* p, float a, float b) {
    asm volatile("st.global.cs.v2.f32 [%0], {%1,%2};" :: "l"(p), "f"(a), "f"(b) : "memory");
}

// ---------------- kernel 0: mask -> bitmap (fast version) ----------------
__global__ __launch_bounds__(256)
void mask_bits(const int* __restrict__ mask)
{
    int gw = blockIdx.x * 8 + (threadIdx.x >> 5);   // 0..65535, 4 words each
    int lane = threadIdx.x & 31;
    int m0 = mask[(size_t)(gw * 4 + 0) * 32 + lane];
    int m1 = mask[(size_t)(gw * 4 + 1) * 32 + lane];
    int m2 = mask[(size_t)(gw * 4 + 2) * 32 + lane];
    int m3 = mask[(size_t)(gw * 4 + 3) * 32 + lane];
    uint32_t b0 = __ballot_sync(0xffffffffu, m0 != 0);
    uint32_t b1 = __ballot_sync(0xffffffffu, m1 != 0);
    uint32_t b2 = __ballot_sync(0xffffffffu, m2 != 0);
    uint32_t b3 = __ballot_sync(0xffffffffu, m3 != 0);
    if (lane == 0) {
        uint32_t* dst = &g_mbits[0][0][0];
        *(uint4*)(dst + gw * 4) = make_uint4(b0, b1, b2, b3);
    }
}

// ---------------- kernel 1: attention (single pass, R9 structure) ----------------
__global__ __launch_bounds__(NTHREADS, 2)
void attn_sp(const float* __restrict__ q,
             const float* __restrict__ k,
             const float* __restrict__ v,
             float* __restrict__ out,
             float* __restrict__ p_attn)
{
    extern __shared__ char smem[];
    uint32_t* KH = (uint32_t*)(smem + OKH);
    uint32_t* KL = (uint32_t*)(smem + OKL);
    uint32_t* VT = (uint32_t*)(smem + OVT);
    uint32_t* PS = (uint32_t*)(smem + OPS);
    float4*   KST = (float4*)(smem + OKST);
    float4*   VST = (float4*)(smem + OVST);
    const uint32_t sbase = smem_u32(smem);

    const int tid  = threadIdx.x;
    const int lane = tid & 31;
    const int wid  = tid >> 5;
    const int lq   = lane >> 2;
    const int cq   = lane & 3;

    const int qt = blockIdx.x;     // 0..15
    const int bh = blockIdx.y;     // 0..31
    const int b  = bh / NH;

    const size_t qoff = ((size_t)bh * SEQ + (size_t)qt * MT) * DIM;
    const float* qg = q + qoff;
    const float4* k4 = (const float4*)(k + (size_t)bh * SEQ * DIM);
    const float4* v4 = (const float4*)(v + (size_t)bh * SEQ * DIM);
    float* outg = out + qoff;
    float* pg   = p_attn + ((size_t)bh * SEQ + (size_t)qt * MT) * SEQ;

    const int qb  = wid * 16;
    const int r0l = qb + lq;
    const int r1l = r0l + 8;

    // ---- issue cp.async for chunk 0 ----
    #pragma unroll
    for (int i = 0; i < 4; ++i) {
        int idx = tid + i * NTHREADS;
        cpasync16(sbase + OKST + 16u * idx, k4 + idx);
        cpasync16(sbase + OVST + 16u * idx, v4 + idx);
    }
    CP_COMMIT();

    // ---- load Q rows r0l/r1l, scale by SLG2E, split to bf16 hi/lo frags ----
    uint32_t Qh[4][4], Ql[4][4];
    #pragma unroll
    for (int s = 0; s < 4; ++s) {
        #pragma unroll
        for (int part = 0; part < 2; ++part) {
            int col = 16 * s + 2 * cq + 8 * part;
            float2 qa = *(const float2*)(qg + r0l * DIM + col);
            float2 qb2 = *(const float2*)(qg + r1l * DIM + col);
            qa.x *= SLG2E; qa.y *= SLG2E; qb2.x *= SLG2E; qb2.y *= SLG2E;
            uint32_t ha = packbf(qa.x, qa.y);
            uint32_t hb = packbf(qb2.x, qb2.y);
            Qh[s][0 + part * 2] = ha;
            Qh[s][1 + part * 2] = hb;
            Ql[s][0 + part * 2] = packbf(qa.x - lo_f(ha), qa.y - hi_f(ha));
            Ql[s][1 + part * 2] = packbf(qb2.x - lo_f(hb), qb2.y - hi_f(hb));
        }
    }

    // ---- mask bitmap row pointers + prefetch chunk 0 bits ----
    const uint32_t* mb0 = &g_mbits[b][qt * MT + r0l][0];
    const uint32_t* mb1 = &g_mbits[b][qt * MT + r1l][0];
    uint2 mc0 = *(const uint2*)(mb0);
    uint2 mc1 = *(const uint2*)(mb1);

    float s0 = 0.f, s1 = 0.f;
    float oa[8][4];
    #pragma unroll
    for (int n = 0; n < 8; ++n)
        oa[n][0] = oa[n][1] = oa[n][2] = oa[n][3] = 0.f;

    for (int c = 0; c < NCH; ++c) {
        CP_WAIT0();
        __syncthreads();    // staging ready AND all warps done with prev KH/KL/VT

        // ---- fill-split K (bf16 hi/lo) and V (tf32) from staging ----
        #pragma unroll
        for (int i = 0; i < 4; ++i) {
            int idx = tid + i * NTHREADS;
            int key = idx >> 4, u = idx & 15;
            float4 kv = KST[idx];
            uint32_t hA = packbf(kv.x, kv.y), hB = packbf(kv.z, kv.w);
            uint32_t lA = packbf(kv.x - lo_f(hA), kv.y - hi_f(hA));
            uint32_t lB = packbf(kv.z - lo_f(hB), kv.w - hi_f(hB));
            *(uint2*)(KH + key * 36 + 2 * u) = make_uint2(hA, hB);
            *(uint2*)(KL + key * 36 + 2 * u) = make_uint2(lA, lB);
            float4 vv = VST[idx];
            uint4 vt;
            vt.x = tf32r(vv.x); vt.y = tf32r(vv.y);
            vt.z = tf32r(vv.z); vt.w = tf32r(vv.w);
            *(uint4*)(VT + key * 72 + 4 * u) = vt;
        }
        __syncthreads();    // split buffers ready; staging free

        // ---- prefetch next chunk (overlaps all compute below) ----
        uint2 mn0 = mc0, mn1 = mc1;
        if (c + 1 < NCH) {
            #pragma unroll
            for (int i = 0; i < 4; ++i) {
                int idx = tid + i * NTHREADS;
                cpasync16(sbase + OKST + 16u * idx, k4 + (c + 1) * 1024 + idx);
                cpasync16(sbase + OVST + 16u * idx, v4 + (c + 1) * 1024 + idx);
            }
            CP_COMMIT();
            mn0 = *(const uint2*)(mb0 + 2 * (c + 1));
            mn1 = *(const uint2*)(mb1 + 2 * (c + 1));
        }

        // ---- QK: bf16 3-term split (hi*hi + hi*lo + lo*hi) ----
        float acc2[2][4][4];
        #pragma unroll
        for (int h = 0; h < 2; ++h)
            #pragma unroll
            for (int n = 0; n < 4; ++n)
                acc2[h][n][0] = acc2[h][n][1] = acc2[h][n][2] = acc2[h][n][3] = 0.f;

        #pragma unroll
        for (int s = 0; s < 4; ++s) {
            #pragma unroll
            for (int h = 0; h < 2; ++h)
                #pragma unroll
                for (int n = 0; n < 4; ++n) {
                    int base = (h * 32 + n * 8 + lq) * 36 + 8 * s + cq;
                    uint32_t bh2[2] = { KH[base], KH[base + 4] };
                    uint32_t bl2[2] = { KL[base], KL[base + 4] };
                    mma16(acc2[h][n], Qh[s], bh2);
                    mma16(acc2[h][n], Qh[s], bl2);
                    mma16(acc2[h][n], Ql[s], bh2);
                }
        }

        // ---- exp (log2-domain, scale pre-folded), s, p~ store, PV ----
        #pragma unroll
        for (int h = 0; h < 2; ++h) {
            uint32_t w0 = (h == 0) ? mc0.x : mc0.y;
            uint32_t w1 = (h == 0) ? mc1.x : mc1.y;
            #pragma unroll
            for (int n = 0; n < 4; ++n) {
                int bp = n * 8 + 2 * cq;
                float p00 = ((w0 >> bp)     & 1u) ? ex2(acc2[h][n][0]) : 0.f;
                float p01 = ((w0 >> (bp+1)) & 1u) ? ex2(acc2[h][n][1]) : 0.f;
                float p10 = ((w1 >> bp)     & 1u) ? ex2(acc2[h][n][2]) : 0.f;
                float p11 = ((w1 >> (bp+1)) & 1u) ? ex2(acc2[h][n][3]) : 0.f;
                s0 += p00 + p01;
                s1 += p10 + p11;
                int colg = c * CHUNK + h * 32 + n * 8 + 2 * cq;
                stg_cs2(pg + (size_t)r0l * SEQ + colg, p00, p01);
                stg_cs2(pg + (size_t)r1l * SEQ + colg, p10, p11);
                *(uint2*)(PS + r0l * 36 + n * 8 + 2 * cq) = make_uint2(tf32r(p00), tf32r(p01));
                *(uint2*)(PS + r1l * 36 + n * 8 + 2 * cq) = make_uint2(tf32r(p10), tf32r(p11));
            }
            __syncwarp();
            #pragma unroll
            for (int kk4 = 0; kk4 < 4; ++kk4) {
                const uint32_t* pp = PS + r0l * 36 + kk4 * 8 + cq;
                uint32_t a[4] = { pp[0], pp[8 * 36], pp[4], pp[8 * 36 + 4] };
                #pragma unroll
                for (int n = 0; n < 8; ++n) {
                    const uint32_t* vp = VT + (h * 32 + kk4 * 8 + cq) * 72 + n * 8 + lq;
                    uint32_t bb[2] = { vp[0], vp[4 * 72] };
                    mma8(oa[n], a, bb);
                }
            }
            __syncwarp();   // PS reuse by h=1
        }

        mc0 = mn0; mc1 = mn1;
    }

    // ---- reduce s across quad lanes ----
    #pragma unroll
    for (int off = 1; off < 4; off <<= 1) {
        s0 += __shfl_xor_sync(0xffffffffu, s0, off);
        s1 += __shfl_xor_sync(0xffffffffu, s1, off);
    }
    const float inv0 = 1.f / s0;
    const float inv1 = 1.f / s1;

    if (cq == 0) {
        g_inv_s[(size_t)bh * SEQ + qt * MT + r0l] = inv0;
        g_inv_s[(size_t)bh * SEQ + qt * MT + r1l] = inv1;
    }

    #pragma unroll
    for (int n = 0; n < 8; ++n) {
        *(float2*)(outg + (size_t)r0l * DIM + n * 8 + 2 * cq) =
            make_float2(oa[n][0] * inv0, oa[n][1] * inv0);
        *(float2*)(outg + (size_t)r1l * DIM + n * 8 + 2 * cq) =
            make_float2(oa[n][2] * inv1, oa[n][3] * inv1);
    }
}

// ---------------- kernel 2: stream-rescale p_attn (.cs hints) ----------------
__global__ __launch_bounds__(256)
void rescale_p(float* __restrict__ p_attn)
{
    unsigned i = blockIdx.x * 256u + threadIdx.x;   // float4 index
    unsigned row = i >> 9;                           // 512 float4 per row
    float inv = g_inv_s[row];
    float4* p4 = (float4*)p_attn + i;
    float a, bb, cc, d;
    asm volatile("ld.global.cs.v4.f32 {%0,%1,%2,%3}, [%4];"
                 : "=f"(a), "=f"(bb), "=f"(cc), "=f"(d) : "l"(p4));
    a *= inv; bb *= inv; cc *= inv; d *= inv;
    asm volatile("st.global.cs.v4.f32 [%0], {%1,%2,%3,%4};"
                 :: "l"(p4), "f"(a), "f"(bb), "f"(cc), "f"(d) : "memory");
}

extern "C" void kernel_launch(void* const* d_in, const int* in_sizes, int n_in,
                              void* d_out, int out_size)
{
    const float* q    = (const float*)d_in[0];
    const float* k    = (const float*)d_in[1];
    const float* v    = (const float*)d_in[2];
    const int*   mask = (const int*)d_in[3];

    float* out    = (float*)d_out;                              // [B,H,S,D]
    float* p_attn = (float*)d_out + (size_t)2 * NH * SEQ * DIM; // [B,H,S,S]

    mask_bits<<<8192, 256>>>(mask);

    cudaFuncSetAttribute(attn_sp,
                         cudaFuncAttributeMaxDynamicSharedMemorySize, SMEM_BYTES);
    dim3 grid(SEQ / MT, 2 * NH);    // (16, 32)
    attn_sp<<<grid, NTHREADS, SMEM_BYTES>>>(q, k, v, out, p_attn);

    rescale_p<<<131072, 256>>>(p_attn);
}

// round 17
// speedup vs baseline: 1.5781x; 1.2372x over previous
#include <cuda_runtime.h>
#include <cuda_fp16.h>
#include <cstdint>

#define NH   16
#define SEQ  2048
#define DIM  64
#define MT   128
#define CHUNK 64
#define NCH  (SEQ / CHUNK)       // 32
#define NTHREADS 256
#define SLG2E 0.18033688011112042f   // 0.125 * log2(e)

// ---- smem byte offsets ----
#define OKH   0u                     // K-hi fp16x2 (d-paired) [64][36] u32  (9216 B)
#define OVT   9216u                  // V fp16x2 (key-paired)  [64][36] u32  (9216 B)
#define OPS   18432u                 // P fp16x2 (key-paired)  [128][36] u32 (18432 B)
#define OKST  36864u                 // K raw staging 16384 B
#define OVST  53248u                 // V raw staging 16384 B
#define SMEM_BYTES 69632u

__device__ float    g_inv_s[2 * NH * SEQ];
__device__ uint32_t g_mbits[2][SEQ][64];      // mask bitmap, 2 MB

// ---------------- helpers ----------------
__device__ __forceinline__ float ex2(float x) {
    float r; asm("ex2.approx.f32 %0, %1;" : "=f"(r) : "f"(x)); return r;
}
__device__ __forceinline__ uint32_t packh2(float a, float b) {   // a -> low half
    __half2 t = __halves2half2(__float2half_rn(a), __float2half_rn(b));
    return *reinterpret_cast<uint32_t*>(&t);
}
__device__ __forceinline__ void mma16f(float* d, const uint32_t* a, const uint32_t* b) {
    asm("mma.sync.aligned.m16n8k16.row.col.f32.f16.f16.f32 "
        "{%0,%1,%2,%3}, {%4,%5,%6,%7}, {%8,%9}, {%0,%1,%2,%3};"
        : "+f"(d[0]), "+f"(d[1]), "+f"(d[2]), "+f"(d[3])
        : "r"(a[0]), "r"(a[1]), "r"(a[2]), "r"(a[3]), "r"(b[0]), "r"(b[1]));
}
__device__ __forceinline__ uint32_t smem_u32(const void* p) {
    uint32_t a;
    asm("{ .reg .u64 t; cvta.to.shared.u64 t, %1; cvt.u32.u64 %0, t; }" : "=r"(a) : "l"(p));
    return a;
}
__device__ __forceinline__ void cpasync16(uint32_t saddr, const void* g) {
    asm volatile("cp.async.cg.shared.global [%0], [%1], 16;" :: "r"(saddr), "l"(g) : "memory");
}
#define CP_COMMIT() asm volatile("cp.async.commit_group;" ::: "memory")
#define CP_WAIT0()  asm volatile("cp.async.wait_group 0;" ::: "memory")

__device__ __forceinline__ void stg_cs2(float* p, float a, float b) {
    asm volatile("st.global.cs.v2.f32 [%0], {%1,%2};" :: "l"(p), "f"(a), "f"(b) : "memory");
}

// ---------------- kernel 0: mask -> bitmap ----------------
__global__ __launch_bounds__(256)
void mask_bits(const int* __restrict__ mask)
{
    int gw = blockIdx.x * 8 + (threadIdx.x >> 5);   // 0..65535, 4 words each
    int lane = threadIdx.x & 31;
    int m0 = mask[(size_t)(gw * 4 + 0) * 32 + lane];
    int m1 = mask[(size_t)(gw * 4 + 1) * 32 + lane];
    int m2 = mask[(size_t)(gw * 4 + 2) * 32 + lane];
    int m3 = mask[(size_t)(gw * 4 + 3) * 32 + lane];
    uint32_t b0 = __ballot_sync(0xffffffffu, m0 != 0);
    uint32_t b1 = __ballot_sync(0xffffffffu, m1 != 0);
    uint32_t b2 = __ballot_sync(0xffffffffu, m2 != 0);
    uint32_t b3 = __ballot_sync(0xffffffffu, m3 != 0);
    if (lane == 0) {
        uint32_t* dst = &g_mbits[0][0][0];
        *(uint4*)(dst + gw * 4) = make_uint4(b0, b1, b2, b3);
    }
}

// ---------------- kernel 1: attention (single pass, fp16 MMA) ----------------
__global__ __launch_bounds__(NTHREADS, 2)
void attn_sp(const float* __restrict__ q,
             const float* __restrict__ k,
             const float* __restrict__ v,
             float* __restrict__ out,
             float* __restrict__ p_attn)
{
    extern __shared__ char smem[];
    uint32_t* KH = (uint32_t*)(smem + OKH);
    uint32_t* VT = (uint32_t*)(smem + OVT);
    uint32_t* PS = (uint32_t*)(smem + OPS);
    float4*   KST = (float4*)(smem + OKST);
    float4*   VST = (float4*)(smem + OVST);
    const uint32_t sbase = smem_u32(smem);

    const int tid  = threadIdx.x;
    const int lane = tid & 31;
    const int wid  = tid >> 5;
    const int lq   = lane >> 2;
    const int cq   = lane & 3;

    const int qt = blockIdx.x;     // 0..15
    const int bh = blockIdx.y;     // 0..31
    const int b  = bh / NH;

    const size_t qoff = ((size_t)bh * SEQ + (size_t)qt * MT) * DIM;
    const float* qg = q + qoff;
    const float4* k4 = (const float4*)(k + (size_t)bh * SEQ * DIM);
    const float4* v4 = (const float4*)(v + (size_t)bh * SEQ * DIM);
    float* outg = out + qoff;
    float* pg   = p_attn + ((size_t)bh * SEQ + (size_t)qt * MT) * SEQ;

    const int qb  = wid * 16;
    const int r0l = qb + lq;
    const int r1l = r0l + 8;

    // ---- issue cp.async for chunk 0 ----
    #pragma unroll
    for (int i = 0; i < 4; ++i) {
        int idx = tid + i * NTHREADS;
        cpasync16(sbase + OKST + 16u * idx, k4 + idx);
        cpasync16(sbase + OVST + 16u * idx, v4 + idx);
    }
    CP_COMMIT();

    // ---- Q rows r0l/r1l: scale, split to fp16 hi/lo A-fragments (regs) ----
    uint32_t Qh[4][4], Ql[4][4];
    #pragma unroll
    for (int s = 0; s < 4; ++s) {
        #pragma unroll
        for (int part = 0; part < 2; ++part) {
            int col = 16 * s + 2 * cq + 8 * part;
            float2 qa  = *(const float2*)(qg + r0l * DIM + col);
            float2 qb2 = *(const float2*)(qg + r1l * DIM + col);
            qa.x *= SLG2E; qa.y *= SLG2E; qb2.x *= SLG2E; qb2.y *= SLG2E;
            __half hax = __float2half_rn(qa.x),  hay = __float2half_rn(qa.y);
            __half hbx = __float2half_rn(qb2.x), hby = __float2half_rn(qb2.y);
            __half2 tA = __halves2half2(hax, hay);
            __half2 tB = __halves2half2(hbx, hby);
            Qh[s][part * 2 + 0] = *reinterpret_cast<uint32_t*>(&tA);
            Qh[s][part * 2 + 1] = *reinterpret_cast<uint32_t*>(&tB);
            Ql[s][part * 2 + 0] = packh2(qa.x - __half2float(hax), qa.y - __half2float(hay));
            Ql[s][part * 2 + 1] = packh2(qb2.x - __half2float(hbx), qb2.y - __half2float(hby));
        }
    }

    const uint32_t* mb0 = &g_mbits[b][qt * MT + r0l][0];
    const uint32_t* mb1 = &g_mbits[b][qt * MT + r1l][0];
    uint2 mc0 = *(const uint2*)(mb0);
    uint2 mc1 = *(const uint2*)(mb1);

    float s0 = 0.f, s1 = 0.f;
    float oa[8][4];
    #pragma unroll
    for (int n = 0; n < 8; ++n)
        oa[n][0] = oa[n][1] = oa[n][2] = oa[n][3] = 0.f;

    for (int c = 0; c < NCH; ++c) {
        CP_WAIT0();
        __syncthreads();    // staging ready AND all warps done with prev KH/VT

        // ---- fill K: fp16 hi, d-paired ----
        #pragma unroll
        for (int i = 0; i < 4; ++i) {
            int idx = tid + i * NTHREADS;
            int key = idx >> 4, u = idx & 15;
            float4 kv = KST[idx];
            uint32_t h0 = packh2(kv.x, kv.y);
            uint32_t h1 = packh2(kv.z, kv.w);
            *(uint2*)(KH + key * 36 + 2 * u) = make_uint2(h0, h1);
        }
        // ---- fill V: fp16, key-paired transpose ----
        #pragma unroll
        for (int i = 0; i < 2; ++i) {
            int m = tid + i * NTHREADS;     // 0..511
            int dblk = m & 15, j = m >> 4;  // j = key pair 0..31
            float4 va = VST[32 * j + dblk];
            float4 vb = VST[32 * j + 16 + dblk];
            int d0 = 4 * dblk;
            VT[(d0 + 0) * 36 + j] = packh2(va.x, vb.x);
            VT[(d0 + 1) * 36 + j] = packh2(va.y, vb.y);
            VT[(d0 + 2) * 36 + j] = packh2(va.z, vb.z);
            VT[(d0 + 3) * 36 + j] = packh2(va.w, vb.w);
        }
        __syncthreads();    // split buffers ready; staging free

        // ---- prefetch next chunk (overlaps compute) ----
        uint2 mn0 = mc0, mn1 = mc1;
        if (c + 1 < NCH) {
            #pragma unroll
            for (int i = 0; i < 4; ++i) {
                int idx = tid + i * NTHREADS;
                cpasync16(sbase + OKST + 16u * idx, k4 + (c + 1) * 1024 + idx);
                cpasync16(sbase + OVST + 16u * idx, v4 + (c + 1) * 1024 + idx);
            }
            CP_COMMIT();
            mn0 = *(const uint2*)(mb0 + 2 * (c + 1));
            mn1 = *(const uint2*)(mb1 + 2 * (c + 1));
        }

        // ---- QK: fp16 2-term (Qh + Ql) x K_hi ----
        float acc2[2][4][4];
        #pragma unroll
        for (int h = 0; h < 2; ++h)
            #pragma unroll
            for (int n = 0; n < 4; ++n)
                acc2[h][n][0] = acc2[h][n][1] = acc2[h][n][2] = acc2[h][n][3] = 0.f;

        #pragma unroll
        for (int s = 0; s < 4; ++s) {
            #pragma unroll
            for (int h = 0; h < 2; ++h)
                #pragma unroll
                for (int n = 0; n < 4; ++n) {
                    int base = (h * 32 + n * 8 + lq) * 36 + 8 * s + cq;
                    uint32_t bb[2] = { KH[base], KH[base + 4] };
                    mma16f(acc2[h][n], Qh[s], bb);
                    mma16f(acc2[h][n], Ql[s], bb);
                }
        }

        // ---- exp, s accumulate, p~ gmem store, PS (fp16) ----
        #pragma unroll
        for (int h = 0; h < 2; ++h) {
            uint32_t w0 = (h == 0) ? mc0.x : mc0.y;
            uint32_t w1 = (h == 0) ? mc1.x : mc1.y;
            #pragma unroll
            for (int n = 0; n < 4; ++n) {
                int bp = n * 8 + 2 * cq;
                float p00 = ((w0 >> bp)     & 1u) ? ex2(acc2[h][n][0]) : 0.f;
                float p01 = ((w0 >> (bp+1)) & 1u) ? ex2(acc2[h][n][1]) : 0.f;
                float p10 = ((w1 >> bp)     & 1u) ? ex2(acc2[h][n][2]) : 0.f;
                float p11 = ((w1 >> (bp+1)) & 1u) ? ex2(acc2[h][n][3]) : 0.f;
                s0 += p00 + p01;
                s1 += p10 + p11;
                int colg = c * CHUNK + h * 32 + n * 8 + 2 * cq;
                stg_cs2(pg + (size_t)r0l * SEQ + colg, p00, p01);
                stg_cs2(pg + (size_t)r1l * SEQ + colg, p10, p11);
                int u0 = h * 16 + n * 4 + cq;
                PS[r0l * 36 + u0] = packh2(p00, p01);
                PS[r1l * 36 + u0] = packh2(p10, p11);
            }
        }
        __syncwarp();   // PS rows are warp-private

        // ---- PV: fp16 1-term, 4 k16-steps x 8 d-tiles ----
        #pragma unroll
        for (int kk = 0; kk < 4; ++kk) {
            uint32_t a[4];
            a[0] = PS[r0l * 36 + 8 * kk + cq];
            a[1] = PS[r1l * 36 + 8 * kk + cq];
            a[2] = PS[r0l * 36 + 8 * kk + cq + 4];
            a[3] = PS[r1l * 36 + 8 * kk + cq + 4];
            #pragma unroll
            for (int n2 = 0; n2 < 8; ++n2) {
                int base = (n2 * 8 + lq) * 36 + 8 * kk + cq;
                uint32_t bb[2] = { VT[base], VT[base + 4] };
                mma16f(oa[n2], a, bb);
            }
        }

        mc0 = mn0; mc1 = mn1;
    }

    // ---- reduce s across quad lanes ----
    #pragma unroll
    for (int off = 1; off < 4; off <<= 1) {
        s0 += __shfl_xor_sync(0xffffffffu, s0, off);
        s1 += __shfl_xor_sync(0xffffffffu, s1, off);
    }
    const float inv0 = 1.f / s0;
    const float inv1 = 1.f / s1;

    if (cq == 0) {
        g_inv_s[(size_t)bh * SEQ + qt * MT + r0l] = inv0;
        g_inv_s[(size_t)bh * SEQ + qt * MT + r1l] = inv1;
    }

    #pragma unroll
    for (int n = 0; n < 8; ++n) {
        *(float2*)(outg + (size_t)r0l * DIM + n * 8 + 2 * cq) =
            make_float2(oa[n][0] * inv0, oa[n][1] * inv0);
        *(float2*)(outg + (size_t)r1l * DIM + n * 8 + 2 * cq) =
            make_float2(oa[n][2] * inv1, oa[n][3] * inv1);
    }
}

// ---------------- kernel 2: stream-rescale p_attn (.cs hints) ----------------
__global__ __launch_bounds__(256)
void rescale_p(float* __restrict__ p_attn)
{
    unsigned i = blockIdx.x * 256u + threadIdx.x;   // float4 index
    unsigned row = i >> 9;                           // 512 float4 per row
    float inv = g_inv_s[row];
    float4* p4 = (float4*)p_attn + i;
    float a, bb, cc, d;
    asm volatile("ld.global.cs.v4.f32 {%0,%1,%2,%3}, [%4];"
                 : "=f"(a), "=f"(bb), "=f"(cc), "=f"(d) : "l"(p4));
    a *= inv; bb *= inv; cc *= inv; d *= inv;
    asm volatile("st.global.cs.v4.f32 [%0], {%1,%2,%3,%4};"
                 :: "l"(p4), "f"(a), "f"(bb), "f"(cc), "f"(d) : "memory");
}

extern "C" void kernel_launch(void* const* d_in, const int* in_sizes, int n_in,
                              void* d_out, int out_size)
{
    const float* q    = (const float*)d_in[0];
    const float* k    = (const float*)d_in[1];
    const float* v    = (const float*)d_in[2];
    const int*   mask = (const int*)d_in[3];

    float* out    = (float*)d_out;                              // [B,H,S,D]
    float* p_attn = (float*)d_out + (size_t)2 * NH * SEQ * DIM; // [B,H,S,S]

    mask_bits<<<8192, 256>>>(mask);

    cudaFuncSetAttribute(attn_sp,
                         cudaFuncAttributeMaxDynamicSharedMemorySize, SMEM_BYTES);
    dim3 grid(SEQ / MT, 2 * NH);    // (16, 32)
    attn_sp<<<grid, NTHREADS, SMEM_BYTES>>>(q, k, v, out, p_attn);

    rescale_p<<<131072, 256>>>(p_attn);
}